// round 6
// baseline (speedup 1.0000x reference)
#include <cuda_runtime.h>
#include <cuda_bf16.h>
#include <cstdint>
#include <math.h>

#define NP 64
#define MM 512
#define DD 256
#define MARGIN 0.2f

__device__ float  g_norm[NP * MM];
__device__ float  g_psum[NP];
__device__ float  g_pcnt[NP];
__device__ float  g_tsort[(size_t)NP * MM * 16];   // per-anchor sorted C values
__device__ float2 g_tsuf [(size_t)NP * MM * 17];   // per-anchor (suffix sum, count)

// off-diagonal tile map (6 tiles of the 4x4 upper triangle), diag = idx-6
__constant__ int c_oby[6] = {0,0,0,1,1,2};
__constant__ int c_obx[6] = {1,2,3,2,3,3};

// ---------------------------------------------------------------------------
__global__ __launch_bounds__(256) void norm_kernel(const float* __restrict__ feat) {
    int row  = (blockIdx.x << 3) + (threadIdx.x >> 5);
    int lane = threadIdx.x & 31;
    const float4* f = reinterpret_cast<const float4*>(feat + (size_t)row * DD);
    float s = 0.f;
#pragma unroll
    for (int u = 0; u < 2; u++) {
        float4 v = f[lane + (u << 5)];
        s += v.x * v.x + v.y * v.y + v.z * v.z + v.w * v.w;
    }
#pragma unroll
    for (int o = 16; o; o >>= 1) s += __shfl_xor_sync(0xffffffffu, s, o);
    if (lane == 0) g_norm[row] = s;
}

// ---------------------------------------------------------------------------
// table kernel: per (part, class) block of 16 anchors, exact fp32 distances,
// rank sort of C = margin + d, suffix sums -> global tables. Also zeros accums.
// ---------------------------------------------------------------------------
__global__ __launch_bounds__(256) void table_kernel(const float* __restrict__ feat) {
    __shared__ float sX[4096];        // [k4][16 rows][4 floats]
    __shared__ float sD[16 * 16];
    __shared__ float sS[16 * 17];
    int b = blockIdx.x;               // 2048
    int p = b >> 5, cls = b & 31;
    int tid = threadIdx.x;
    if (tid == 0 && cls == 0) { g_psum[p] = 0.f; g_pcnt[p] = 0.f; }
    const float* base = feat + ((size_t)p * MM + cls * 16) * DD;
#pragma unroll
    for (int it = 0; it < 4; it++) {
        int seg = tid + (it << 8);
        int row = seg >> 6, k4 = seg & 63;
        float4 v = *reinterpret_cast<const float4*>(base + (size_t)row * DD + (k4 << 2));
        *reinterpret_cast<float4*>(&sX[((k4 << 4) + row) << 2]) = v;
    }
    __syncthreads();
    int i = tid >> 4, j = tid & 15;
    float acc = 0.f;
#pragma unroll
    for (int k4 = 0; k4 < 64; k4++) {
        float4 xi = *reinterpret_cast<const float4*>(&sX[((k4 << 4) + i) << 2]);
        float4 xj = *reinterpret_cast<const float4*>(&sX[((k4 << 4) + j) << 2]);
        float d0 = xi.x - xj.x, d1 = xi.y - xj.y;
        float d2 = xi.z - xj.z, d3 = xi.w - xj.w;
        acc = fmaf(d0, d0, acc); acc = fmaf(d1, d1, acc);
        acc = fmaf(d2, d2, acc); acc = fmaf(d3, d3, acc);
    }
    sD[tid] = MARGIN + sqrtf(acc);
    __syncthreads();
    if (tid < 16) {
        const float* v = &sD[tid * 16];
#pragma unroll
        for (int k = 0; k < 16; k++) {
            float vk = v[k];
            int r = 0;
#pragma unroll
            for (int jj = 0; jj < 16; jj++) {
                float vj = v[jj];
                r += (int)((vj < vk) | ((vj == vk) & (jj < k)));
            }
            sS[tid * 17 + r] = vk;
        }
        size_t ab = (size_t)p * MM + cls * 16 + tid;
        float ss = 0.f;
        g_tsuf[ab * 17 + 16] = make_float2(0.f, 0.f);
#pragma unroll
        for (int k = 15; k >= 0; k--) {
            float sv = sS[tid * 17 + k];
            ss += sv;
            g_tsuf[ab * 17 + k] = make_float2(ss, (float)(16 - k));
            g_tsort[ab * 16 + k] = sv;
        }
    }
}

// ---------------------------------------------------------------------------
__device__ __forceinline__ uint32_t smem_u32(const void* p) {
    uint32_t a;
    asm("{ .reg .u64 t; cvta.to.shared.u64 t, %1; cvt.u32.u64 %0, t; }" : "=r"(a) : "l"(p));
    return a;
}

__device__ __forceinline__ void split2(float x0, float x1, uint32_t& hi, uint32_t& lo) {
    uint32_t h;
    asm("cvt.rn.bf16x2.f32 %0, %1, %2;" : "=r"(h) : "f"(x1), "f"(x0));
    float h0 = __uint_as_float(h << 16);
    float h1 = __uint_as_float(h & 0xFFFF0000u);
    float r0 = x0 - h0, r1 = x1 - h1;
    asm("cvt.rn.bf16x2.f32 %0, %1, %2;" : "=r"(lo) : "f"(r1), "f"(r0));
    hi = h;
}

#define MMA16816(c0,c1,c2,c3, a0,a1,a2,a3, b0,b1) \
    asm volatile("mma.sync.aligned.m16n8k16.row.col.f32.bf16.bf16.f32 " \
                 "{%0,%1,%2,%3}, {%4,%5,%6,%7}, {%8,%9}, {%0,%1,%2,%3};" \
                 : "+f"(c0), "+f"(c1), "+f"(c2), "+f"(c3) \
                 : "r"(a0), "r"(a1), "r"(a2), "r"(a3), "r"(b0), "r"(b1))

__device__ __forceinline__ void cpa16(uint32_t s, const void* g) {
    asm volatile("cp.async.ca.shared.global [%0], [%1], 16;" :: "r"(s), "l"(g) : "memory");
}

// SMEM layout
#define LDA 40
#define OFF_AHI 0
#define OFF_ALO 10240
#define OFF_BHI 20480
#define OFF_BLO 30720                 // operand tiles end 40960
#define OFF_RAWA 40960                // 2 bufs x 16384 -> 73728
#define OFF_RAWB 73728                // 2 bufs x 16384 -> 106496
#define OFF_SR  40960                 // overlay on raw (post-mainloop)
#define OFF_TR  49664
#define OFF_SC  67072
#define OFF_TC  75776                 // -> 93184
#define OFF_NRM 106496                // 256 floats
#define OFF_RED 107520                // 16 floats
#define SMEM_TOTAL 107584

__device__ __forceinline__ void stage(uint32_t sb, const float* __restrict__ A,
                                      const float* __restrict__ B,
                                      int ch, int buf, int tid, bool diag) {
    int k0 = ch << 5;
    uint32_t ra = sb + OFF_RAWA + (buf << 14);
#pragma unroll
    for (int it = 0; it < 4; it++) {
        int seg = tid + (it << 8);
        cpa16(ra + (seg << 4), A + (size_t)(seg >> 3) * DD + k0 + ((seg & 7) << 2));
    }
    if (!diag) {
        uint32_t rb = sb + OFF_RAWB + (buf << 14);
#pragma unroll
        for (int it = 0; it < 4; it++) {
            int seg = tid + (it << 8);
            cpa16(rb + (seg << 4), B + (size_t)(seg >> 3) * DD + k0 + ((seg & 7) << 2));
        }
    }
}

__device__ __forceinline__ void conv_one(char* smem, int raw_off, int hi_off, int lo_off, int tid) {
    const float4* ra = reinterpret_cast<const float4*>(smem + raw_off);
    uint16_t* shi = reinterpret_cast<uint16_t*>(smem + hi_off);
    uint16_t* slo = reinterpret_cast<uint16_t*>(smem + lo_off);
#pragma unroll
    for (int it = 0; it < 4; it++) {
        int seg = tid + (it << 8);
        float4 v = ra[seg];
        uint32_t h0, h1, l0, l1;
        split2(v.x, v.y, h0, l0);
        split2(v.z, v.w, h1, l1);
        int idx = (seg >> 3) * LDA + ((seg & 7) << 2);
        *reinterpret_cast<uint2*>(&shi[idx]) = make_uint2(h0, h1);
        *reinterpret_cast<uint2*>(&slo[idx]) = make_uint2(l0, l1);
    }
}

__device__ __forceinline__ void search2(
    const float* __restrict__ S, const float2* __restrict__ T,
    float s7, float s15, float d, float& aA, float& aB, float& aC)
{
    int idx = (s7 <= d) ? 8 : 0;
    idx += (S[idx + 3] <= d) ? 4 : 0;
    idx += (S[idx + 1] <= d) ? 2 : 0;
    idx += (S[idx]     <= d) ? 1 : 0;
    idx = (s15 <= d) ? 16 : idx;
    float2 t = T[idx];
    aA += t.x;
    aB  = fmaf(t.y, d, aB);
    aC += t.y;
}

// ---------------------------------------------------------------------------
// uniform fused GEMM + hinge, grid (10, 64): x<6 off-diag, x>=6 diag(x-6)
// ---------------------------------------------------------------------------
__global__ void __launch_bounds__(256, 2) fused_kernel(const float* __restrict__ feat) {
    extern __shared__ char smem[];
    const int tid = threadIdx.x;
    const int w = tid >> 5, lane = tid & 31;
    const int g = lane >> 2, tg = lane & 3;
    const int wm = w >> 1, wn = w & 1;
    const int p = blockIdx.y;
    const bool diag = (blockIdx.x >= 6);
    const int by = diag ? (blockIdx.x - 6) : c_oby[blockIdx.x];
    const int bx = diag ? (blockIdx.x - 6) : c_obx[blockIdx.x];
    uint32_t sb = smem_u32(smem);

    float* sNi = reinterpret_cast<float*>(smem + OFF_NRM);
    float* sNj = sNi + 128;
    if (tid < 128) {
        sNi[tid] = g_norm[p * MM + by * 128 + tid];
        sNj[tid] = diag ? sNi[tid] : g_norm[p * MM + bx * 128 + tid];
    }

    const float* Abase = feat + ((size_t)p * MM + (size_t)by * 128) * DD;
    const float* Bbase = feat + ((size_t)p * MM + (size_t)bx * 128) * DD;

    const uint16_t* sAhi = reinterpret_cast<const uint16_t*>(smem + OFF_AHI);
    const uint16_t* sAlo = reinterpret_cast<const uint16_t*>(smem + OFF_ALO);
    const uint16_t* sBhi = reinterpret_cast<const uint16_t*>(smem + (diag ? OFF_AHI : OFF_BHI));
    const uint16_t* sBlo = reinterpret_cast<const uint16_t*>(smem + (diag ? OFF_ALO : OFF_BLO));

    float c[2][8][4];
#pragma unroll
    for (int mi = 0; mi < 2; mi++)
#pragma unroll
        for (int ni = 0; ni < 8; ni++)
#pragma unroll
            for (int r = 0; r < 4; r++) c[mi][ni][r] = 0.f;

    stage(sb, Abase, Bbase, 0, 0, tid, diag);
    asm volatile("cp.async.commit_group;" ::: "memory");

#pragma unroll 1
    for (int ch = 0; ch < 8; ch++) {
        if (ch < 7) {
            stage(sb, Abase, Bbase, ch + 1, (ch + 1) & 1, tid, diag);
            asm volatile("cp.async.commit_group;" ::: "memory");
            asm volatile("cp.async.wait_group 1;" ::: "memory");
        } else {
            asm volatile("cp.async.wait_group 0;" ::: "memory");
        }
        __syncthreads();
        int buf = ch & 1;
        conv_one(smem, OFF_RAWA + (buf << 14), OFF_AHI, OFF_ALO, tid);
        if (!diag) conv_one(smem, OFF_RAWB + (buf << 14), OFF_BHI, OFF_BLO, tid);
        __syncthreads();

#pragma unroll
        for (int ks = 0; ks < 2; ks++) {
            int kk = (ks << 4) + (tg << 1);
            uint32_t ah[2][4], al[2][4];
#pragma unroll
            for (int mi = 0; mi < 2; mi++) {
                int r0 = ((wm << 5) + (mi << 4) + g) * LDA + kk;
                int r1 = r0 + (LDA << 3);
                ah[mi][0] = *reinterpret_cast<const uint32_t*>(&sAhi[r0]);
                ah[mi][1] = *reinterpret_cast<const uint32_t*>(&sAhi[r1]);
                ah[mi][2] = *reinterpret_cast<const uint32_t*>(&sAhi[r0 + 8]);
                ah[mi][3] = *reinterpret_cast<const uint32_t*>(&sAhi[r1 + 8]);
                al[mi][0] = *reinterpret_cast<const uint32_t*>(&sAlo[r0]);
                al[mi][1] = *reinterpret_cast<const uint32_t*>(&sAlo[r1]);
                al[mi][2] = *reinterpret_cast<const uint32_t*>(&sAlo[r0 + 8]);
                al[mi][3] = *reinterpret_cast<const uint32_t*>(&sAlo[r1 + 8]);
            }
            uint32_t bh[8][2], bl[8][2];
#pragma unroll
            for (int ni = 0; ni < 8; ni++) {
                int rb = ((wn << 6) + (ni << 3) + g) * LDA + kk;
                bh[ni][0] = *reinterpret_cast<const uint32_t*>(&sBhi[rb]);
                bh[ni][1] = *reinterpret_cast<const uint32_t*>(&sBhi[rb + 8]);
                bl[ni][0] = *reinterpret_cast<const uint32_t*>(&sBlo[rb]);
                bl[ni][1] = *reinterpret_cast<const uint32_t*>(&sBlo[rb + 8]);
            }
#pragma unroll
            for (int mi = 0; mi < 2; mi++)
#pragma unroll
                for (int ni = 0; ni < 8; ni++) {
                    MMA16816(c[mi][ni][0], c[mi][ni][1], c[mi][ni][2], c[mi][ni][3],
                             ah[mi][0], ah[mi][1], ah[mi][2], ah[mi][3],
                             bh[ni][0], bh[ni][1]);
                    MMA16816(c[mi][ni][0], c[mi][ni][1], c[mi][ni][2], c[mi][ni][3],
                             ah[mi][0], ah[mi][1], ah[mi][2], ah[mi][3],
                             bl[ni][0], bl[ni][1]);
                    MMA16816(c[mi][ni][0], c[mi][ni][1], c[mi][ni][2], c[mi][ni][3],
                             al[mi][0], al[mi][1], al[mi][2], al[mi][3],
                             bh[ni][0], bh[ni][1]);
                }
        }
    }
    __syncthreads();   // mainloop done; raw region reusable as tables

    float*  sSR = reinterpret_cast<float*>(smem + OFF_SR);
    float2* sTR = reinterpret_cast<float2*>(smem + OFF_TR);
    float*  sSC = reinterpret_cast<float*>(smem + OFF_SC);
    float2* sTC = reinterpret_cast<float2*>(smem + OFF_TC);

    {   // table loads (latency overlapped with distance transform below)
        size_t rb16 = ((size_t)p * MM + by * 128) * 16;
        size_t rb17 = ((size_t)p * MM + by * 128) * 17;
        for (int q = tid; q < 2048; q += 256)
            sSR[(q >> 4) * 17 + (q & 15)] = g_tsort[rb16 + q];
        for (int q = tid; q < 2176; q += 256)
            sTR[q] = g_tsuf[rb17 + q];
        if (!diag) {
            size_t cb16 = ((size_t)p * MM + bx * 128) * 16;
            size_t cb17 = ((size_t)p * MM + bx * 128) * 17;
            for (int q = tid; q < 2048; q += 256)
                sSC[(q >> 4) * 17 + (q & 15)] = g_tsort[cb16 + q];
            for (int q = tid; q < 2176; q += 256)
                sTC[q] = g_tsuf[cb17 + q];
        }
    }

    // distances in place of accumulators
#pragma unroll
    for (int mi = 0; mi < 2; mi++) {
        int i0 = (wm << 5) + (mi << 4) + g;
#pragma unroll
        for (int ni = 0; ni < 8; ni++) {
            int j0 = (wn << 6) + (ni << 3) + (tg << 1);
            c[mi][ni][0] = sqrtf(fmaxf(sNi[i0]     + sNj[j0]     - 2.f * c[mi][ni][0], 0.f));
            c[mi][ni][1] = sqrtf(fmaxf(sNi[i0]     + sNj[j0 + 1] - 2.f * c[mi][ni][1], 0.f));
            c[mi][ni][2] = sqrtf(fmaxf(sNi[i0 + 8] + sNj[j0]     - 2.f * c[mi][ni][2], 0.f));
            c[mi][ni][3] = sqrtf(fmaxf(sNi[i0 + 8] + sNj[j0 + 1] - 2.f * c[mi][ni][3], 0.f));
        }
    }
    __syncthreads();

    // hinge searches: row anchors hoisted; col S7/S15 hoisted per column
    const int abase = wm << 5;
    int aIdx[4] = {abase + g, abase + g + 8, abase + 16 + g, abase + 24 + g};
    const float*  SR[4]; const float2* TR[4];
    float S7[4], S15[4];
#pragma unroll
    for (int q = 0; q < 4; q++) {
        SR[q]  = &sSR[aIdx[q] * 17];
        TR[q]  = &sTR[aIdx[q] * 17];
        S7[q]  = SR[q][7];
        S15[q] = SR[q][15];
    }
    float aA = 0.f, aB = 0.f, aC = 0.f;
#pragma unroll
    for (int ni = 0; ni < 8; ni++) {
#pragma unroll
        for (int e = 0; e < 2; e++) {
            int j = (wn << 6) + (ni << 3) + (tg << 1) + e;
            float c7 = 0.f, c15 = 0.f;
            const float* SCj = &sSC[j * 17];
            const float2* TCj = &sTC[j * 17];
            if (!diag) { c7 = SCj[7]; c15 = SCj[15]; }
            int jc = j >> 4;
#pragma unroll
            for (int mi = 0; mi < 2; mi++) {
                float d0 = c[mi][ni][e];
                float d1 = c[mi][ni][2 + e];
                const int q0 = mi << 1, q1 = q0 + 1;
                bool ok0 = !diag || ((aIdx[q0] >> 4) != jc);
                bool ok1 = !diag || ((aIdx[q1] >> 4) != jc);
                if (ok0) search2(SR[q0], TR[q0], S7[q0], S15[q0], d0, aA, aB, aC);
                if (ok1) search2(SR[q1], TR[q1], S7[q1], S15[q1], d1, aA, aB, aC);
                if (!diag) {
                    search2(SCj, TCj, c7, c15, d0, aA, aB, aC);
                    search2(SCj, TCj, c7, c15, d1, aA, aB, aC);
                }
            }
        }
    }

    float loss = aA - aB, cnt = aC;
#pragma unroll
    for (int o = 16; o; o >>= 1) {
        loss += __shfl_xor_sync(0xffffffffu, loss, o);
        cnt  += __shfl_xor_sync(0xffffffffu, cnt, o);
    }
    float* sRed = reinterpret_cast<float*>(smem + OFF_RED);
    if (lane == 0) { sRed[w] = loss; sRed[8 + w] = cnt; }
    __syncthreads();
    if (tid == 0) {
        float L = 0.f, C = 0.f;
#pragma unroll
        for (int k = 0; k < 8; k++) { L += sRed[k]; C += sRed[8 + k]; }
        atomicAdd(&g_psum[p], L);
        atomicAdd(&g_pcnt[p], C);
    }
}

// ---------------------------------------------------------------------------
__global__ void final_kernel(float* __restrict__ out, int out_size) {
    __shared__ float sa[2], sb2[2];
    int t = threadIdx.x;          // 64 threads
    float cnt = g_pcnt[t], sum = g_psum[t];
    float a = (cnt > 0.f) ? sum / fmaxf(cnt, 1.f) : 0.f;
    float b = cnt;
#pragma unroll
    for (int o = 16; o; o >>= 1) {
        a += __shfl_xor_sync(0xffffffffu, a, o);
        b += __shfl_xor_sync(0xffffffffu, b, o);
    }
    if ((t & 31) == 0) { sa[t >> 5] = a; sb2[t >> 5] = b; }
    __syncthreads();
    if (t == 0) {
        out[0] = (sa[0] + sa[1]) / (float)NP;
        if (out_size > 1) out[1] = (sb2[0] + sb2[1]) / (float)NP;
    }
}

extern "C" void kernel_launch(void* const* d_in, const int* in_sizes, int n_in,
                              void* d_out, int out_size) {
    const float* feat = (const float*)d_in[0];
    (void)in_sizes; (void)n_in;

    cudaFuncSetAttribute(fused_kernel, cudaFuncAttributeMaxDynamicSharedMemorySize, SMEM_TOTAL);

    norm_kernel<<<4096, 256>>>(feat);
    table_kernel<<<2048, 256>>>(feat);
    dim3 gf(10, NP);
    fused_kernel<<<gf, 256, SMEM_TOTAL>>>(feat);
    final_kernel<<<1, 64>>>((float*)d_out, out_size);
}

// round 7
// speedup vs baseline: 1.0291x; 1.0291x over previous
#include <cuda_runtime.h>
#include <cuda_bf16.h>
#include <cstdint>
#include <math.h>

#define NP 64
#define MM 512
#define DD 256
#define MARGIN 0.2f

__device__ float  g_norm[NP * MM];
__device__ float  g_psum[NP];
__device__ float  g_pcnt[NP];
__device__ float  g_tsort[(size_t)NP * MM * 16];   // per-anchor sorted C values
__device__ float2 g_tsuf [(size_t)NP * MM * 17];   // per-anchor (suffix sum, count)

// off-diagonal tile map (6 tiles of the 4x4 upper triangle), diag = idx-6
__constant__ int c_oby[6] = {0,0,0,1,1,2};
__constant__ int c_obx[6] = {1,2,3,2,3,3};

// ---------------------------------------------------------------------------
// table kernel: per (part, class) block of 16 anchors -> exact fp32 distances,
// rank sort of C = margin + d, suffix sums -> global tables. Also computes the
// row norms for this block (feature data already staged in smem) and zeros
// the per-part accumulators.
// ---------------------------------------------------------------------------
__global__ __launch_bounds__(256) void table_kernel(const float* __restrict__ feat) {
    __shared__ float sX[4096];        // [k4][16 rows][4 floats]
    __shared__ float sD[16 * 16];
    __shared__ float sS[16 * 17];
    int b = blockIdx.x;               // 2048
    int p = b >> 5, cls = b & 31;
    int tid = threadIdx.x;
    if (tid == 0 && cls == 0) { g_psum[p] = 0.f; g_pcnt[p] = 0.f; }
    const float* base = feat + ((size_t)p * MM + cls * 16) * DD;
#pragma unroll
    for (int it = 0; it < 4; it++) {
        int seg = tid + (it << 8);
        int row = seg >> 6, k4 = seg & 63;
        float4 v = *reinterpret_cast<const float4*>(base + (size_t)row * DD + (k4 << 2));
        *reinterpret_cast<float4*>(&sX[((k4 << 4) + row) << 2]) = v;
    }
    __syncthreads();
    int i = tid >> 4, j = tid & 15;
    float acc = 0.f;
#pragma unroll
    for (int k4 = 0; k4 < 64; k4++) {
        float4 xi = *reinterpret_cast<const float4*>(&sX[((k4 << 4) + i) << 2]);
        float4 xj = *reinterpret_cast<const float4*>(&sX[((k4 << 4) + j) << 2]);
        float d0 = xi.x - xj.x, d1 = xi.y - xj.y;
        float d2 = xi.z - xj.z, d3 = xi.w - xj.w;
        acc = fmaf(d0, d0, acc); acc = fmaf(d1, d1, acc);
        acc = fmaf(d2, d2, acc); acc = fmaf(d3, d3, acc);
    }
    sD[tid] = MARGIN + sqrtf(acc);
    // norms for this block's 16 rows (threads 0..15)
    if (tid < 16) {
        float ns = 0.f;
#pragma unroll
        for (int k4 = 0; k4 < 64; k4++) {
            float4 x = *reinterpret_cast<const float4*>(&sX[((k4 << 4) + tid) << 2]);
            ns = fmaf(x.x, x.x, ns); ns = fmaf(x.y, x.y, ns);
            ns = fmaf(x.z, x.z, ns); ns = fmaf(x.w, x.w, ns);
        }
        g_norm[p * MM + cls * 16 + tid] = ns;
    }
    __syncthreads();
    if (tid < 16) {
        const float* v = &sD[tid * 16];
#pragma unroll
        for (int k = 0; k < 16; k++) {
            float vk = v[k];
            int r = 0;
#pragma unroll
            for (int jj = 0; jj < 16; jj++) {
                float vj = v[jj];
                r += (int)((vj < vk) | ((vj == vk) & (jj < k)));
            }
            sS[tid * 17 + r] = vk;
        }
        size_t ab = (size_t)p * MM + cls * 16 + tid;
        float ss = 0.f;
        g_tsuf[ab * 17 + 16] = make_float2(0.f, 0.f);
#pragma unroll
        for (int k = 15; k >= 0; k--) {
            float sv = sS[tid * 17 + k];
            ss += sv;
            g_tsuf[ab * 17 + k] = make_float2(ss, (float)(16 - k));
            g_tsort[ab * 16 + k] = sv;
        }
    }
}

// ---------------------------------------------------------------------------
__device__ __forceinline__ void split2(float x0, float x1, uint32_t& hi, uint32_t& lo) {
    uint32_t h;
    asm("cvt.rn.bf16x2.f32 %0, %1, %2;" : "=r"(h) : "f"(x1), "f"(x0));
    float h0 = __uint_as_float(h << 16);
    float h1 = __uint_as_float(h & 0xFFFF0000u);
    float r0 = x0 - h0, r1 = x1 - h1;
    asm("cvt.rn.bf16x2.f32 %0, %1, %2;" : "=r"(lo) : "f"(r1), "f"(r0));
    hi = h;
}

#define MMA16816(c0,c1,c2,c3, a0,a1,a2,a3, b0,b1) \
    asm volatile("mma.sync.aligned.m16n8k16.row.col.f32.bf16.bf16.f32 " \
                 "{%0,%1,%2,%3}, {%4,%5,%6,%7}, {%8,%9}, {%0,%1,%2,%3};" \
                 : "+f"(c0), "+f"(c1), "+f"(c2), "+f"(c3) \
                 : "r"(a0), "r"(a1), "r"(a2), "r"(a3), "r"(b0), "r"(b1))

// SMEM layout. Mainloop operands [0, 40960); epilogue tables overlay after a
// barrier. Norms/reduce live above, no overlap.
#define LDA 40
#define TILE_B (128 * LDA * 2)        // 10240
#define OFF_AHI 0
#define OFF_ALO (TILE_B)
#define OFF_BHI (2 * TILE_B)
#define OFF_BLO (3 * TILE_B)          // operands end at 40960
#define OFF_SR  0                     // float [128*17]
#define OFF_TR  8704                  // float2[128*17]
#define OFF_SC  26112                 // float [128*17]
#define OFF_TC  34816                 // float2[128*17] -> 52224
#define OFF_NRM 52224                 // 256 floats
#define OFF_RED 53248                 // 16 floats
#define SMEM_TOTAL 53440

__device__ __forceinline__ void load_chunk(
    const float* __restrict__ src, int k0, char* smem, int off_hi, int off_lo, int tid)
{
    uint16_t* shi = reinterpret_cast<uint16_t*>(smem + off_hi);
    uint16_t* slo = reinterpret_cast<uint16_t*>(smem + off_lo);
#pragma unroll
    for (int it = 0; it < 4; it++) {
        int q   = tid + (it << 8);
        int row = q >> 3;
        int c4  = q & 7;
        float4 v = *reinterpret_cast<const float4*>(src + (size_t)row * DD + k0 + (c4 << 2));
        uint32_t h0, h1, l0, l1;
        split2(v.x, v.y, h0, l0);
        split2(v.z, v.w, h1, l1);
        int idx = row * LDA + (c4 << 2);
        *reinterpret_cast<uint2*>(&shi[idx]) = make_uint2(h0, h1);
        *reinterpret_cast<uint2*>(&slo[idx]) = make_uint2(l0, l1);
    }
}

__device__ __forceinline__ void search2(
    const float* __restrict__ S, const float2* __restrict__ T,
    float s7, float s15, float d, float& aA, float& aB, float& aC)
{
    int idx = (s7 <= d) ? 8 : 0;
    idx += (S[idx + 3] <= d) ? 4 : 0;
    idx += (S[idx + 1] <= d) ? 2 : 0;
    idx += (S[idx]     <= d) ? 1 : 0;
    idx = (s15 <= d) ? 16 : idx;
    float2 t = T[idx];
    aA += t.x;
    aB  = fmaf(t.y, d, aB);
    aC += t.y;
}

// ---------------------------------------------------------------------------
// uniform fused GEMM + hinge, grid (10, 64): x<6 off-diag, x>=6 diag(x-6)
// ---------------------------------------------------------------------------
__global__ void __launch_bounds__(256, 2) fused_kernel(const float* __restrict__ feat) {
    extern __shared__ char smem[];
    const int tid = threadIdx.x;
    const int w = tid >> 5, lane = tid & 31;
    const int g = lane >> 2, tg = lane & 3;
    const int wm = w >> 1, wn = w & 1;
    const int p = blockIdx.y;
    const bool diag = (blockIdx.x >= 6);
    const int by = diag ? (blockIdx.x - 6) : c_oby[blockIdx.x];
    const int bx = diag ? (blockIdx.x - 6) : c_obx[blockIdx.x];

    float* sNi = reinterpret_cast<float*>(smem + OFF_NRM);
    float* sNj = sNi + 128;
    if (tid < 128) {
        sNi[tid] = g_norm[p * MM + by * 128 + tid];
        sNj[tid] = diag ? sNi[tid] : g_norm[p * MM + bx * 128 + tid];
    }

    const float* Abase = feat + ((size_t)p * MM + (size_t)by * 128) * DD;
    const float* Bbase = feat + ((size_t)p * MM + (size_t)bx * 128) * DD;

    const uint16_t* sAhi = reinterpret_cast<const uint16_t*>(smem + OFF_AHI);
    const uint16_t* sAlo = reinterpret_cast<const uint16_t*>(smem + OFF_ALO);
    const uint16_t* sBhi = reinterpret_cast<const uint16_t*>(smem + (diag ? OFF_AHI : OFF_BHI));
    const uint16_t* sBlo = reinterpret_cast<const uint16_t*>(smem + (diag ? OFF_ALO : OFF_BLO));

    float c[2][8][4];
#pragma unroll
    for (int mi = 0; mi < 2; mi++)
#pragma unroll
        for (int ni = 0; ni < 8; ni++)
#pragma unroll
            for (int r = 0; r < 4; r++) c[mi][ni][r] = 0.f;

#pragma unroll 1
    for (int ch = 0; ch < 8; ch++) {
        int k0 = ch << 5;
        __syncthreads();
        load_chunk(Abase, k0, smem, OFF_AHI, OFF_ALO, tid);
        if (!diag) load_chunk(Bbase, k0, smem, OFF_BHI, OFF_BLO, tid);
        __syncthreads();

#pragma unroll
        for (int ks = 0; ks < 2; ks++) {
            int kk = (ks << 4) + (tg << 1);
            uint32_t ah[2][4], al[2][4];
#pragma unroll
            for (int mi = 0; mi < 2; mi++) {
                int r0 = ((wm << 5) + (mi << 4) + g) * LDA + kk;
                int r1 = r0 + (LDA << 3);
                ah[mi][0] = *reinterpret_cast<const uint32_t*>(&sAhi[r0]);
                ah[mi][1] = *reinterpret_cast<const uint32_t*>(&sAhi[r1]);
                ah[mi][2] = *reinterpret_cast<const uint32_t*>(&sAhi[r0 + 8]);
                ah[mi][3] = *reinterpret_cast<const uint32_t*>(&sAhi[r1 + 8]);
                al[mi][0] = *reinterpret_cast<const uint32_t*>(&sAlo[r0]);
                al[mi][1] = *reinterpret_cast<const uint32_t*>(&sAlo[r1]);
                al[mi][2] = *reinterpret_cast<const uint32_t*>(&sAlo[r0 + 8]);
                al[mi][3] = *reinterpret_cast<const uint32_t*>(&sAlo[r1 + 8]);
            }
            uint32_t bh[8][2], bl[8][2];
#pragma unroll
            for (int ni = 0; ni < 8; ni++) {
                int rb = ((wn << 6) + (ni << 3) + g) * LDA + kk;
                bh[ni][0] = *reinterpret_cast<const uint32_t*>(&sBhi[rb]);
                bh[ni][1] = *reinterpret_cast<const uint32_t*>(&sBhi[rb + 8]);
                bl[ni][0] = *reinterpret_cast<const uint32_t*>(&sBlo[rb]);
                bl[ni][1] = *reinterpret_cast<const uint32_t*>(&sBlo[rb + 8]);
            }
#pragma unroll
            for (int mi = 0; mi < 2; mi++)
#pragma unroll
                for (int ni = 0; ni < 8; ni++) {
                    MMA16816(c[mi][ni][0], c[mi][ni][1], c[mi][ni][2], c[mi][ni][3],
                             ah[mi][0], ah[mi][1], ah[mi][2], ah[mi][3],
                             bh[ni][0], bh[ni][1]);
                    MMA16816(c[mi][ni][0], c[mi][ni][1], c[mi][ni][2], c[mi][ni][3],
                             ah[mi][0], ah[mi][1], ah[mi][2], ah[mi][3],
                             bl[ni][0], bl[ni][1]);
                    MMA16816(c[mi][ni][0], c[mi][ni][1], c[mi][ni][2], c[mi][ni][3],
                             al[mi][0], al[mi][1], al[mi][2], al[mi][3],
                             bh[ni][0], bh[ni][1]);
                }
        }
    }
    __syncthreads();   // operand smem dead; tables overlay it

    float*  sSR = reinterpret_cast<float*>(smem + OFF_SR);
    float2* sTR = reinterpret_cast<float2*>(smem + OFF_TR);
    float*  sSC = reinterpret_cast<float*>(smem + OFF_SC);
    float2* sTC = reinterpret_cast<float2*>(smem + OFF_TC);

    {   // table loads (latency overlapped with the distance transform below)
        size_t rb16 = ((size_t)p * MM + by * 128) * 16;
        size_t rb17 = ((size_t)p * MM + by * 128) * 17;
        for (int q = tid; q < 2048; q += 256)
            sSR[(q >> 4) * 17 + (q & 15)] = g_tsort[rb16 + q];
        for (int q = tid; q < 2176; q += 256)
            sTR[q] = g_tsuf[rb17 + q];
        if (!diag) {
            size_t cb16 = ((size_t)p * MM + bx * 128) * 16;
            size_t cb17 = ((size_t)p * MM + bx * 128) * 17;
            for (int q = tid; q < 2048; q += 256)
                sSC[(q >> 4) * 17 + (q & 15)] = g_tsort[cb16 + q];
            for (int q = tid; q < 2176; q += 256)
                sTC[q] = g_tsuf[cb17 + q];
        }
    }

    // distances in place of accumulators
#pragma unroll
    for (int mi = 0; mi < 2; mi++) {
        int i0 = (wm << 5) + (mi << 4) + g;
#pragma unroll
        for (int ni = 0; ni < 8; ni++) {
            int j0 = (wn << 6) + (ni << 3) + (tg << 1);
            c[mi][ni][0] = sqrtf(fmaxf(sNi[i0]     + sNj[j0]     - 2.f * c[mi][ni][0], 0.f));
            c[mi][ni][1] = sqrtf(fmaxf(sNi[i0]     + sNj[j0 + 1] - 2.f * c[mi][ni][1], 0.f));
            c[mi][ni][2] = sqrtf(fmaxf(sNi[i0 + 8] + sNj[j0]     - 2.f * c[mi][ni][2], 0.f));
            c[mi][ni][3] = sqrtf(fmaxf(sNi[i0 + 8] + sNj[j0 + 1] - 2.f * c[mi][ni][3], 0.f));
        }
    }
    __syncthreads();

    // hinge searches: row anchors hoisted; col S7/S15 hoisted per column
    const int abase = wm << 5;
    int aIdx[4] = {abase + g, abase + g + 8, abase + 16 + g, abase + 24 + g};
    const float*  SR[4]; const float2* TR[4];
    float S7[4], S15[4];
#pragma unroll
    for (int q = 0; q < 4; q++) {
        SR[q]  = &sSR[aIdx[q] * 17];
        TR[q]  = &sTR[aIdx[q] * 17];
        S7[q]  = SR[q][7];
        S15[q] = SR[q][15];
    }
    float aA = 0.f, aB = 0.f, aC = 0.f;
#pragma unroll
    for (int ni = 0; ni < 8; ni++) {
#pragma unroll
        for (int e = 0; e < 2; e++) {
            int j = (wn << 6) + (ni << 3) + (tg << 1) + e;
            float c7 = 0.f, c15 = 0.f;
            const float* SCj = &sSC[j * 17];
            const float2* TCj = &sTC[j * 17];
            if (!diag) { c7 = SCj[7]; c15 = SCj[15]; }
            int jc = j >> 4;
#pragma unroll
            for (int mi = 0; mi < 2; mi++) {
                float d0 = c[mi][ni][e];
                float d1 = c[mi][ni][2 + e];
                const int q0 = mi << 1, q1 = q0 + 1;
                bool ok0 = !diag || ((aIdx[q0] >> 4) != jc);
                bool ok1 = !diag || ((aIdx[q1] >> 4) != jc);
                if (ok0) search2(SR[q0], TR[q0], S7[q0], S15[q0], d0, aA, aB, aC);
                if (ok1) search2(SR[q1], TR[q1], S7[q1], S15[q1], d1, aA, aB, aC);
                if (!diag) {
                    search2(SCj, TCj, c7, c15, d0, aA, aB, aC);
                    search2(SCj, TCj, c7, c15, d1, aA, aB, aC);
                }
            }
        }
    }

    float loss = aA - aB, cnt = aC;
#pragma unroll
    for (int o = 16; o; o >>= 1) {
        loss += __shfl_xor_sync(0xffffffffu, loss, o);
        cnt  += __shfl_xor_sync(0xffffffffu, cnt, o);
    }
    float* sRed = reinterpret_cast<float*>(smem + OFF_RED);
    if (lane == 0) { sRed[w] = loss; sRed[8 + w] = cnt; }
    __syncthreads();
    if (tid == 0) {
        float L = 0.f, C = 0.f;
#pragma unroll
        for (int k = 0; k < 8; k++) { L += sRed[k]; C += sRed[8 + k]; }
        atomicAdd(&g_psum[p], L);
        atomicAdd(&g_pcnt[p], C);
    }
}

// ---------------------------------------------------------------------------
__global__ void final_kernel(float* __restrict__ out, int out_size) {
    __shared__ float sa[2], sb2[2];
    int t = threadIdx.x;          // 64 threads
    float cnt = g_pcnt[t], sum = g_psum[t];
    float a = (cnt > 0.f) ? sum / fmaxf(cnt, 1.f) : 0.f;
    float b = cnt;
#pragma unroll
    for (int o = 16; o; o >>= 1) {
        a += __shfl_xor_sync(0xffffffffu, a, o);
        b += __shfl_xor_sync(0xffffffffu, b, o);
    }
    if ((t & 31) == 0) { sa[t >> 5] = a; sb2[t >> 5] = b; }
    __syncthreads();
    if (t == 0) {
        out[0] = (sa[0] + sa[1]) / (float)NP;
        if (out_size > 1) out[1] = (sb2[0] + sb2[1]) / (float)NP;
    }
}

extern "C" void kernel_launch(void* const* d_in, const int* in_sizes, int n_in,
                              void* d_out, int out_size) {
    const float* feat = (const float*)d_in[0];
    (void)in_sizes; (void)n_in;

    cudaFuncSetAttribute(fused_kernel, cudaFuncAttributeMaxDynamicSharedMemorySize, SMEM_TOTAL);

    table_kernel<<<2048, 256>>>(feat);
    dim3 gf(10, NP);
    fused_kernel<<<gf, 256, SMEM_TOTAL>>>(feat);
    final_kernel<<<1, 64>>>((float*)d_out, out_size);
}

// round 8
// speedup vs baseline: 1.1104x; 1.0791x over previous
#include <cuda_runtime.h>
#include <cuda_bf16.h>
#include <cstdint>
#include <math.h>

#define NP 64
#define MM 512
#define DD 256
#define MARGIN 0.2f

__device__ float  g_norm[NP * MM];
__device__ float  g_psum[NP];
__device__ float  g_pcnt[NP];
__device__ float  g_tsort[(size_t)NP * MM * 16];   // per-anchor sorted C values
__device__ float2 g_tsuf [(size_t)NP * MM * 17];   // per-anchor (suffix sum, count)

// off-diagonal tile map (6 tiles of the 4x4 upper triangle), diag = idx-6
__constant__ int c_oby[6] = {0,0,0,1,1,2};
__constant__ int c_obx[6] = {1,2,3,2,3,3};

// ---------------------------------------------------------------------------
// table kernel v2: one warp per class. Register-blocked gram (2x4 pairs per
// thread, 32 FMA per k4 from 6 LDS.128), XOR-swizzled smem, norms fused in.
// ---------------------------------------------------------------------------
#define TK_OFF_X 0          // 8 cls x 2048 floats  = 65536 B
#define TK_OFF_D 65536      // 8 cls x 256 floats   = 8192 B
#define TK_OFF_S 73728      // 8 cls x 272 floats   = 8704 B
#define TK_OFF_N 82432      // 8 cls x 16 floats    = 512 B
#define TK_SMEM  82944

#define G4(A, XI, XJ) \
    A = fmaf(XI.x, XJ.x, A); A = fmaf(XI.y, XJ.y, A); \
    A = fmaf(XI.z, XJ.z, A); A = fmaf(XI.w, XJ.w, A);

__global__ __launch_bounds__(256) void table_kernel(const float* __restrict__ feat) {
    extern __shared__ char sm[];
    float* sX = reinterpret_cast<float*>(sm + TK_OFF_X);   // [cls][kc(32)][row^sw][4]
    float* sD = reinterpret_cast<float*>(sm + TK_OFF_D);
    float* sS = reinterpret_cast<float*>(sm + TK_OFF_S);
    float* sN = reinterpret_cast<float*>(sm + TK_OFF_N);
    const int b   = blockIdx.x;        // 256 blocks: 64 parts x 4 groups
    const int p   = b >> 2;
    const int grp = (b & 3) << 3;      // first of this block's 8 classes
    const int tid = threadIdx.x;
    const int wcls = tid >> 5, lane = tid & 31;
    const int a = lane & 7, bj = lane >> 3;
    if (tid == 0 && (b & 3) == 0) { g_psum[p] = 0.f; g_pcnt[p] = 0.f; }

    float acc[2][4];
#pragma unroll
    for (int u = 0; u < 2; u++)
#pragma unroll
        for (int v = 0; v < 4; v++) acc[u][v] = 0.f;
    float nrm = 0.f;

    const float* Xc = sX + wcls * 2048;

#pragma unroll 1
    for (int c0 = 0; c0 < 2; c0++) {
        __syncthreads();
        // stage 8 classes x 16 rows x 128 floats, coalesced; swizzled store
#pragma unroll
        for (int it = 0; it < 16; it++) {
            int q = tid + (it << 8);
            int kc = q & 31, row = (q >> 5) & 15, cls = q >> 9;
            float4 v = *reinterpret_cast<const float4*>(feat
                + ((size_t)p * MM + (grp + cls) * 16 + row) * DD + (c0 << 7) + (kc << 2));
            *reinterpret_cast<float4*>(sX + cls * 2048 + kc * 64
                + ((row ^ (kc & 15)) << 2)) = v;
        }
        __syncthreads();
#pragma unroll 8
        for (int kc = 0; kc < 32; kc++) {
            const float* K = Xc + kc * 64;
            const int sw = kc & 15;
            float4 xi0 = *reinterpret_cast<const float4*>(K + ((a        ^ sw) << 2));
            float4 xi1 = *reinterpret_cast<const float4*>(K + (((a + 8)  ^ sw) << 2));
            float4 xj0 = *reinterpret_cast<const float4*>(K + (((bj*4+0) ^ sw) << 2));
            float4 xj1 = *reinterpret_cast<const float4*>(K + (((bj*4+1) ^ sw) << 2));
            float4 xj2 = *reinterpret_cast<const float4*>(K + (((bj*4+2) ^ sw) << 2));
            float4 xj3 = *reinterpret_cast<const float4*>(K + (((bj*4+3) ^ sw) << 2));
            G4(acc[0][0], xi0, xj0); G4(acc[0][1], xi0, xj1);
            G4(acc[0][2], xi0, xj2); G4(acc[0][3], xi0, xj3);
            G4(acc[1][0], xi1, xj0); G4(acc[1][1], xi1, xj1);
            G4(acc[1][2], xi1, xj2); G4(acc[1][3], xi1, xj3);
        }
        if (lane < 16) {
#pragma unroll 8
            for (int kc = 0; kc < 32; kc++) {
                float4 x = *reinterpret_cast<const float4*>(Xc + kc * 64
                    + ((lane ^ (kc & 15)) << 2));
                nrm = fmaf(x.x, x.x, nrm); nrm = fmaf(x.y, x.y, nrm);
                nrm = fmaf(x.z, x.z, nrm); nrm = fmaf(x.w, x.w, nrm);
            }
        }
    }
    if (lane < 16) sN[(wcls << 4) + lane] = nrm;
    __syncwarp();

    // distances for this thread's 2x4 pairs
#pragma unroll
    for (int u = 0; u < 2; u++) {
        int i = a + (u << 3);
        float ni = sN[(wcls << 4) + i];
#pragma unroll
        for (int v = 0; v < 4; v++) {
            int j = (bj << 2) + v;
            float d2 = fmaxf(ni + sN[(wcls << 4) + j] - 2.f * acc[u][v], 0.f);
            sD[(wcls << 8) + (i << 4) + j] = MARGIN + sqrtf(d2);
        }
    }
    __syncwarp();

    // per-anchor rank sort + suffix sums; publish tables + norms
    if (lane < 16) {
        const float* vv = &sD[(wcls << 8) + (lane << 4)];
        float* ss = &sS[wcls * 272 + lane * 17];
#pragma unroll
        for (int k = 0; k < 16; k++) {
            float vk = vv[k];
            int r = 0;
#pragma unroll
            for (int jj = 0; jj < 16; jj++) {
                float vj = vv[jj];
                r += (int)((vj < vk) | ((vj == vk) & (jj < k)));
            }
            ss[r] = vk;
        }
        size_t ab = (size_t)p * MM + (grp + wcls) * 16 + lane;
        g_norm[ab] = nrm;
        float run = 0.f;
        g_tsuf[ab * 17 + 16] = make_float2(0.f, 0.f);
#pragma unroll
        for (int k = 15; k >= 0; k--) {
            run += ss[k];
            g_tsuf[ab * 17 + k] = make_float2(run, (float)(16 - k));
            g_tsort[ab * 16 + k] = ss[k];
        }
    }
}

// ---------------------------------------------------------------------------
__device__ __forceinline__ void split2(float x0, float x1, uint32_t& hi, uint32_t& lo) {
    uint32_t h;
    asm("cvt.rn.bf16x2.f32 %0, %1, %2;" : "=r"(h) : "f"(x1), "f"(x0));
    float h0 = __uint_as_float(h << 16);
    float h1 = __uint_as_float(h & 0xFFFF0000u);
    float r0 = x0 - h0, r1 = x1 - h1;
    asm("cvt.rn.bf16x2.f32 %0, %1, %2;" : "=r"(lo) : "f"(r1), "f"(r0));
    hi = h;
}

#define MMA16816(c0,c1,c2,c3, a0,a1,a2,a3, b0,b1) \
    asm volatile("mma.sync.aligned.m16n8k16.row.col.f32.bf16.bf16.f32 " \
                 "{%0,%1,%2,%3}, {%4,%5,%6,%7}, {%8,%9}, {%0,%1,%2,%3};" \
                 : "+f"(c0), "+f"(c1), "+f"(c2), "+f"(c3) \
                 : "r"(a0), "r"(a1), "r"(a2), "r"(a3), "r"(b0), "r"(b1))

// SMEM layout. Mainloop operands [0, 40960); epilogue tables overlay after a
// barrier. Norms/reduce live above, no overlap.
#define LDA 40
#define TILE_B (128 * LDA * 2)        // 10240
#define OFF_AHI 0
#define OFF_ALO (TILE_B)
#define OFF_BHI (2 * TILE_B)
#define OFF_BLO (3 * TILE_B)          // operands end at 40960
#define OFF_SR  0                     // float [128*17]
#define OFF_TR  8704                  // float2[128*17]
#define OFF_SC  26112                 // float [128*17]
#define OFF_TC  34816                 // float2[128*17] -> 52224
#define OFF_NRM 52224                 // 256 floats
#define OFF_RED 53248                 // 16 floats
#define SMEM_TOTAL 53440

__device__ __forceinline__ void load_chunk(
    const float* __restrict__ src, int k0, char* smem, int off_hi, int off_lo, int tid)
{
    uint16_t* shi = reinterpret_cast<uint16_t*>(smem + off_hi);
    uint16_t* slo = reinterpret_cast<uint16_t*>(smem + off_lo);
#pragma unroll
    for (int it = 0; it < 4; it++) {
        int q   = tid + (it << 8);
        int row = q >> 3;
        int c4  = q & 7;
        float4 v = *reinterpret_cast<const float4*>(src + (size_t)row * DD + k0 + (c4 << 2));
        uint32_t h0, h1, l0, l1;
        split2(v.x, v.y, h0, l0);
        split2(v.z, v.w, h1, l1);
        int idx = row * LDA + (c4 << 2);
        *reinterpret_cast<uint2*>(&shi[idx]) = make_uint2(h0, h1);
        *reinterpret_cast<uint2*>(&slo[idx]) = make_uint2(l0, l1);
    }
}

__device__ __forceinline__ void search2(
    const float* __restrict__ S, const float2* __restrict__ T,
    float s7, float s15, float d, float& aA, float& aB, float& aC)
{
    int idx = (s7 <= d) ? 8 : 0;
    idx += (S[idx + 3] <= d) ? 4 : 0;
    idx += (S[idx + 1] <= d) ? 2 : 0;
    idx += (S[idx]     <= d) ? 1 : 0;
    idx = (s15 <= d) ? 16 : idx;
    float2 t = T[idx];
    aA += t.x;
    aB  = fmaf(t.y, d, aB);
    aC += t.y;
}

// ---------------------------------------------------------------------------
// uniform fused GEMM + hinge, grid (10, 64): x<6 off-diag, x>=6 diag(x-6)
// ---------------------------------------------------------------------------
__global__ void __launch_bounds__(256, 2) fused_kernel(const float* __restrict__ feat) {
    extern __shared__ char smem[];
    const int tid = threadIdx.x;
    const int w = tid >> 5, lane = tid & 31;
    const int g = lane >> 2, tg = lane & 3;
    const int wm = w >> 1, wn = w & 1;
    const int p = blockIdx.y;
    const bool diag = (blockIdx.x >= 6);
    const int by = diag ? (blockIdx.x - 6) : c_oby[blockIdx.x];
    const int bx = diag ? (blockIdx.x - 6) : c_obx[blockIdx.x];

    float* sNi = reinterpret_cast<float*>(smem + OFF_NRM);
    float* sNj = sNi + 128;
    if (tid < 128) {
        sNi[tid] = g_norm[p * MM + by * 128 + tid];
        sNj[tid] = diag ? sNi[tid] : g_norm[p * MM + bx * 128 + tid];
    }

    const float* Abase = feat + ((size_t)p * MM + (size_t)by * 128) * DD;
    const float* Bbase = feat + ((size_t)p * MM + (size_t)bx * 128) * DD;

    const uint16_t* sAhi = reinterpret_cast<const uint16_t*>(smem + OFF_AHI);
    const uint16_t* sAlo = reinterpret_cast<const uint16_t*>(smem + OFF_ALO);
    const uint16_t* sBhi = reinterpret_cast<const uint16_t*>(smem + (diag ? OFF_AHI : OFF_BHI));
    const uint16_t* sBlo = reinterpret_cast<const uint16_t*>(smem + (diag ? OFF_ALO : OFF_BLO));

    float c[2][8][4];
#pragma unroll
    for (int mi = 0; mi < 2; mi++)
#pragma unroll
        for (int ni = 0; ni < 8; ni++)
#pragma unroll
            for (int r = 0; r < 4; r++) c[mi][ni][r] = 0.f;

#pragma unroll 1
    for (int ch = 0; ch < 8; ch++) {
        int k0 = ch << 5;
        __syncthreads();
        load_chunk(Abase, k0, smem, OFF_AHI, OFF_ALO, tid);
        if (!diag) load_chunk(Bbase, k0, smem, OFF_BHI, OFF_BLO, tid);
        __syncthreads();

#pragma unroll
        for (int ks = 0; ks < 2; ks++) {
            int kk = (ks << 4) + (tg << 1);
            uint32_t ah[2][4], al[2][4];
#pragma unroll
            for (int mi = 0; mi < 2; mi++) {
                int r0 = ((wm << 5) + (mi << 4) + g) * LDA + kk;
                int r1 = r0 + (LDA << 3);
                ah[mi][0] = *reinterpret_cast<const uint32_t*>(&sAhi[r0]);
                ah[mi][1] = *reinterpret_cast<const uint32_t*>(&sAhi[r1]);
                ah[mi][2] = *reinterpret_cast<const uint32_t*>(&sAhi[r0 + 8]);
                ah[mi][3] = *reinterpret_cast<const uint32_t*>(&sAhi[r1 + 8]);
                al[mi][0] = *reinterpret_cast<const uint32_t*>(&sAlo[r0]);
                al[mi][1] = *reinterpret_cast<const uint32_t*>(&sAlo[r1]);
                al[mi][2] = *reinterpret_cast<const uint32_t*>(&sAlo[r0 + 8]);
                al[mi][3] = *reinterpret_cast<const uint32_t*>(&sAlo[r1 + 8]);
            }
            uint32_t bh[8][2], bl[8][2];
#pragma unroll
            for (int ni = 0; ni < 8; ni++) {
                int rb = ((wn << 6) + (ni << 3) + g) * LDA + kk;
                bh[ni][0] = *reinterpret_cast<const uint32_t*>(&sBhi[rb]);
                bh[ni][1] = *reinterpret_cast<const uint32_t*>(&sBhi[rb + 8]);
                bl[ni][0] = *reinterpret_cast<const uint32_t*>(&sBlo[rb]);
                bl[ni][1] = *reinterpret_cast<const uint32_t*>(&sBlo[rb + 8]);
            }
#pragma unroll
            for (int mi = 0; mi < 2; mi++)
#pragma unroll
                for (int ni = 0; ni < 8; ni++) {
                    MMA16816(c[mi][ni][0], c[mi][ni][1], c[mi][ni][2], c[mi][ni][3],
                             ah[mi][0], ah[mi][1], ah[mi][2], ah[mi][3],
                             bh[ni][0], bh[ni][1]);
                    MMA16816(c[mi][ni][0], c[mi][ni][1], c[mi][ni][2], c[mi][ni][3],
                             ah[mi][0], ah[mi][1], ah[mi][2], ah[mi][3],
                             bl[ni][0], bl[ni][1]);
                    MMA16816(c[mi][ni][0], c[mi][ni][1], c[mi][ni][2], c[mi][ni][3],
                             al[mi][0], al[mi][1], al[mi][2], al[mi][3],
                             bh[ni][0], bh[ni][1]);
                }
        }
    }
    __syncthreads();   // operand smem dead; tables overlay it

    float*  sSR = reinterpret_cast<float*>(smem + OFF_SR);
    float2* sTR = reinterpret_cast<float2*>(smem + OFF_TR);
    float*  sSC = reinterpret_cast<float*>(smem + OFF_SC);
    float2* sTC = reinterpret_cast<float2*>(smem + OFF_TC);

    {   // table loads (latency overlapped with the distance transform below)
        size_t rb16 = ((size_t)p * MM + by * 128) * 16;
        size_t rb17 = ((size_t)p * MM + by * 128) * 17;
        for (int q = tid; q < 2048; q += 256)
            sSR[(q >> 4) * 17 + (q & 15)] = g_tsort[rb16 + q];
        for (int q = tid; q < 2176; q += 256)
            sTR[q] = g_tsuf[rb17 + q];
        if (!diag) {
            size_t cb16 = ((size_t)p * MM + bx * 128) * 16;
            size_t cb17 = ((size_t)p * MM + bx * 128) * 17;
            for (int q = tid; q < 2048; q += 256)
                sSC[(q >> 4) * 17 + (q & 15)] = g_tsort[cb16 + q];
            for (int q = tid; q < 2176; q += 256)
                sTC[q] = g_tsuf[cb17 + q];
        }
    }

    // distances in place of accumulators
#pragma unroll
    for (int mi = 0; mi < 2; mi++) {
        int i0 = (wm << 5) + (mi << 4) + g;
#pragma unroll
        for (int ni = 0; ni < 8; ni++) {
            int j0 = (wn << 6) + (ni << 3) + (tg << 1);
            c[mi][ni][0] = sqrtf(fmaxf(sNi[i0]     + sNj[j0]     - 2.f * c[mi][ni][0], 0.f));
            c[mi][ni][1] = sqrtf(fmaxf(sNi[i0]     + sNj[j0 + 1] - 2.f * c[mi][ni][1], 0.f));
            c[mi][ni][2] = sqrtf(fmaxf(sNi[i0 + 8] + sNj[j0]     - 2.f * c[mi][ni][2], 0.f));
            c[mi][ni][3] = sqrtf(fmaxf(sNi[i0 + 8] + sNj[j0 + 1] - 2.f * c[mi][ni][3], 0.f));
        }
    }
    __syncthreads();

    // hinge searches: row anchors hoisted; col S7/S15 hoisted per column
    const int abase = wm << 5;
    int aIdx[4] = {abase + g, abase + g + 8, abase + 16 + g, abase + 24 + g};
    const float*  SR[4]; const float2* TR[4];
    float S7[4], S15[4];
#pragma unroll
    for (int q = 0; q < 4; q++) {
        SR[q]  = &sSR[aIdx[q] * 17];
        TR[q]  = &sTR[aIdx[q] * 17];
        S7[q]  = SR[q][7];
        S15[q] = SR[q][15];
    }
    float aA = 0.f, aB = 0.f, aC = 0.f;
#pragma unroll
    for (int ni = 0; ni < 8; ni++) {
#pragma unroll
        for (int e = 0; e < 2; e++) {
            int j = (wn << 6) + (ni << 3) + (tg << 1) + e;
            float c7 = 0.f, c15 = 0.f;
            const float* SCj = &sSC[j * 17];
            const float2* TCj = &sTC[j * 17];
            if (!diag) { c7 = SCj[7]; c15 = SCj[15]; }
            int jc = j >> 4;
#pragma unroll
            for (int mi = 0; mi < 2; mi++) {
                float d0 = c[mi][ni][e];
                float d1 = c[mi][ni][2 + e];
                const int q0 = mi << 1, q1 = q0 + 1;
                bool ok0 = !diag || ((aIdx[q0] >> 4) != jc);
                bool ok1 = !diag || ((aIdx[q1] >> 4) != jc);
                if (ok0) search2(SR[q0], TR[q0], S7[q0], S15[q0], d0, aA, aB, aC);
                if (ok1) search2(SR[q1], TR[q1], S7[q1], S15[q1], d1, aA, aB, aC);
                if (!diag) {
                    search2(SCj, TCj, c7, c15, d0, aA, aB, aC);
                    search2(SCj, TCj, c7, c15, d1, aA, aB, aC);
                }
            }
        }
    }

    float loss = aA - aB, cnt = aC;
#pragma unroll
    for (int o = 16; o; o >>= 1) {
        loss += __shfl_xor_sync(0xffffffffu, loss, o);
        cnt  += __shfl_xor_sync(0xffffffffu, cnt, o);
    }
    float* sRed = reinterpret_cast<float*>(smem + OFF_RED);
    if (lane == 0) { sRed[w] = loss; sRed[8 + w] = cnt; }
    __syncthreads();
    if (tid == 0) {
        float L = 0.f, C = 0.f;
#pragma unroll
        for (int k = 0; k < 8; k++) { L += sRed[k]; C += sRed[8 + k]; }
        atomicAdd(&g_psum[p], L);
        atomicAdd(&g_pcnt[p], C);
    }
}

// ---------------------------------------------------------------------------
__global__ void final_kernel(float* __restrict__ out, int out_size) {
    __shared__ float sa[2], sb2[2];
    int t = threadIdx.x;          // 64 threads
    float cnt = g_pcnt[t], sum = g_psum[t];
    float a = (cnt > 0.f) ? sum / fmaxf(cnt, 1.f) : 0.f;
    float b = cnt;
#pragma unroll
    for (int o = 16; o; o >>= 1) {
        a += __shfl_xor_sync(0xffffffffu, a, o);
        b += __shfl_xor_sync(0xffffffffu, b, o);
    }
    if ((t & 31) == 0) { sa[t >> 5] = a; sb2[t >> 5] = b; }
    __syncthreads();
    if (t == 0) {
        out[0] = (sa[0] + sa[1]) / (float)NP;
        if (out_size > 1) out[1] = (sb2[0] + sb2[1]) / (float)NP;
    }
}

extern "C" void kernel_launch(void* const* d_in, const int* in_sizes, int n_in,
                              void* d_out, int out_size) {
    const float* feat = (const float*)d_in[0];
    (void)in_sizes; (void)n_in;

    cudaFuncSetAttribute(table_kernel, cudaFuncAttributeMaxDynamicSharedMemorySize, TK_SMEM);
    cudaFuncSetAttribute(fused_kernel, cudaFuncAttributeMaxDynamicSharedMemorySize, SMEM_TOTAL);

    table_kernel<<<256, 256, TK_SMEM>>>(feat);
    dim3 gf(10, NP);
    fused_kernel<<<gf, 256, SMEM_TOTAL>>>(feat);
    final_kernel<<<1, 64>>>((float*)d_out, out_size);
}

// round 9
// speedup vs baseline: 1.2666x; 1.1406x over previous
#include <cuda_runtime.h>
#include <cuda_bf16.h>
#include <cstdint>
#include <math.h>

#define NP 64
#define MM 512
#define DD 256
#define MARGIN 0.2f

__device__ float  g_norm[NP * MM];
__device__ float  g_psum[NP];
__device__ float  g_pcnt[NP];
__device__ float  g_tsort[(size_t)NP * MM * 16];   // per-anchor sorted C values
__device__ float2 g_tsuf [(size_t)NP * MM * 17];   // per-anchor (suffix sum, count)
__device__ int    g_ready[NP * 4];                 // per (part, diag block) flag

// off-diagonal tile map (6 tiles of the 4x4 upper triangle)
__constant__ int c_oby[6] = {0,0,0,1,1,2};
__constant__ int c_obx[6] = {1,2,3,2,3,3};

// ---------------------------------------------------------------------------
// norms + zero flags/accumulators
// ---------------------------------------------------------------------------
__global__ __launch_bounds__(256) void norm_prep_kernel(const float* __restrict__ feat) {
    int row  = (blockIdx.x << 3) + (threadIdx.x >> 5);
    int lane = threadIdx.x & 31;
    const float4* f = reinterpret_cast<const float4*>(feat + (size_t)row * DD);
    float s = 0.f;
#pragma unroll
    for (int u = 0; u < 2; u++) {
        float4 v = f[lane + (u << 5)];
        s += v.x * v.x + v.y * v.y + v.z * v.z + v.w * v.w;
    }
#pragma unroll
    for (int o = 16; o; o >>= 1) s += __shfl_xor_sync(0xffffffffu, s, o);
    if (lane == 0) g_norm[row] = s;
    if (blockIdx.x == 0) {
        int t = threadIdx.x;
        g_ready[t] = 0;
        if (t < NP) { g_psum[t] = 0.f; g_pcnt[t] = 0.f; }
    }
}

// ---------------------------------------------------------------------------
__device__ __forceinline__ void split2(float x0, float x1, uint32_t& hi, uint32_t& lo) {
    uint32_t h;
    asm("cvt.rn.bf16x2.f32 %0, %1, %2;" : "=r"(h) : "f"(x1), "f"(x0));
    float h0 = __uint_as_float(h << 16);
    float h1 = __uint_as_float(h & 0xFFFF0000u);
    float r0 = x0 - h0, r1 = x1 - h1;
    asm("cvt.rn.bf16x2.f32 %0, %1, %2;" : "=r"(lo) : "f"(r1), "f"(r0));
    hi = h;
}

#define MMA16816(c0,c1,c2,c3, a0,a1,a2,a3, b0,b1) \
    asm volatile("mma.sync.aligned.m16n8k16.row.col.f32.bf16.bf16.f32 " \
                 "{%0,%1,%2,%3}, {%4,%5,%6,%7}, {%8,%9}, {%0,%1,%2,%3};" \
                 : "+f"(c0), "+f"(c1), "+f"(c2), "+f"(c3) \
                 : "r"(a0), "r"(a1), "r"(a2), "r"(a3), "r"(b0), "r"(b1))

// SMEM layout. Mainloop operands [0, 40960); epilogue tables overlay after a
// barrier. Norms/reduce live above, no overlap.
#define LDA 40
#define TILE_B (128 * LDA * 2)        // 10240
#define OFF_AHI 0
#define OFF_ALO (TILE_B)
#define OFF_BHI (2 * TILE_B)
#define OFF_BLO (3 * TILE_B)          // operands end at 40960
#define OFF_SR  0                     // float [128*17]
#define OFF_TR  8704                  // float2[128*17]
#define OFF_SC  26112                 // float [128*17] (diag: sPos 128*16)
#define OFF_TC  34816                 // float2[128*17] -> 52224
#define OFF_NRM 52224                 // 256 floats
#define OFF_RED 53248                 // 16 floats
#define SMEM_TOTAL 53440

__device__ __forceinline__ void load_chunk(
    const float* __restrict__ src, int k0, char* smem, int off_hi, int off_lo, int tid)
{
    uint16_t* shi = reinterpret_cast<uint16_t*>(smem + off_hi);
    uint16_t* slo = reinterpret_cast<uint16_t*>(smem + off_lo);
#pragma unroll
    for (int it = 0; it < 4; it++) {
        int q   = tid + (it << 8);
        int row = q >> 3;
        int c4  = q & 7;
        float4 v = *reinterpret_cast<const float4*>(src + (size_t)row * DD + k0 + (c4 << 2));
        uint32_t h0, h1, l0, l1;
        split2(v.x, v.y, h0, l0);
        split2(v.z, v.w, h1, l1);
        int idx = row * LDA + (c4 << 2);
        *reinterpret_cast<uint2*>(&shi[idx]) = make_uint2(h0, h1);
        *reinterpret_cast<uint2*>(&slo[idx]) = make_uint2(l0, l1);
    }
}

__device__ __forceinline__ void search2(
    const float* __restrict__ S, const float2* __restrict__ T,
    float s7, float s15, float d, float& aA, float& aB, float& aC)
{
    int idx = (s7 <= d) ? 8 : 0;
    idx += (S[idx + 3] <= d) ? 4 : 0;
    idx += (S[idx + 1] <= d) ? 2 : 0;
    idx += (S[idx]     <= d) ? 1 : 0;
    idx = (s15 <= d) ? 16 : idx;
    float2 t = T[idx];
    aA += t.x;
    aB  = fmaf(t.y, d, aB);
    aC += t.y;
}

// ---------------------------------------------------------------------------
// fused GEMM + table build (diag) + hinge. 1-D grid of 640:
//   bid < 256  -> diag:    p = bid>>2, by = bx = bid&3 (flag index = bid)
//   bid >= 256 -> offdiag: q = bid-256, p = q/6, tile = q%6
// Diag CTAs publish per-anchor tables then release g_ready; off-diag CTAs
// acquire-spin on the two flags before their table load.
// ---------------------------------------------------------------------------
__global__ void __launch_bounds__(256, 2) fused_kernel(const float* __restrict__ feat) {
    extern __shared__ char smem[];
    const int tid = threadIdx.x;
    const int w = tid >> 5, lane = tid & 31;
    const int g = lane >> 2, tg = lane & 3;
    const int wm = w >> 1, wn = w & 1;
    const int bid = blockIdx.x;
    const bool diag = (bid < 256);
    int p, by, bx;
    if (diag) {
        p = bid >> 2; by = bx = bid & 3;
    } else {
        int q = bid - 256;
        p = q / 6;
        int t = q - p * 6;
        by = c_oby[t]; bx = c_obx[t];
    }

    float* sNi = reinterpret_cast<float*>(smem + OFF_NRM);
    float* sNj = sNi + 128;
    if (tid < 128) {
        sNi[tid] = g_norm[p * MM + by * 128 + tid];
        sNj[tid] = diag ? sNi[tid] : g_norm[p * MM + bx * 128 + tid];
    }

    const float* Abase = feat + ((size_t)p * MM + (size_t)by * 128) * DD;
    const float* Bbase = feat + ((size_t)p * MM + (size_t)bx * 128) * DD;

    const uint16_t* sAhi = reinterpret_cast<const uint16_t*>(smem + OFF_AHI);
    const uint16_t* sAlo = reinterpret_cast<const uint16_t*>(smem + OFF_ALO);
    const uint16_t* sBhi = reinterpret_cast<const uint16_t*>(smem + (diag ? OFF_AHI : OFF_BHI));
    const uint16_t* sBlo = reinterpret_cast<const uint16_t*>(smem + (diag ? OFF_ALO : OFF_BLO));

    float c[2][8][4];
#pragma unroll
    for (int mi = 0; mi < 2; mi++)
#pragma unroll
        for (int ni = 0; ni < 8; ni++)
#pragma unroll
            for (int r = 0; r < 4; r++) c[mi][ni][r] = 0.f;

#pragma unroll 1
    for (int ch = 0; ch < 8; ch++) {
        int k0 = ch << 5;
        __syncthreads();
        load_chunk(Abase, k0, smem, OFF_AHI, OFF_ALO, tid);
        if (!diag) load_chunk(Bbase, k0, smem, OFF_BHI, OFF_BLO, tid);
        __syncthreads();

#pragma unroll
        for (int ks = 0; ks < 2; ks++) {
            int kk = (ks << 4) + (tg << 1);
            uint32_t ah[2][4], al[2][4];
#pragma unroll
            for (int mi = 0; mi < 2; mi++) {
                int r0 = ((wm << 5) + (mi << 4) + g) * LDA + kk;
                int r1 = r0 + (LDA << 3);
                ah[mi][0] = *reinterpret_cast<const uint32_t*>(&sAhi[r0]);
                ah[mi][1] = *reinterpret_cast<const uint32_t*>(&sAhi[r1]);
                ah[mi][2] = *reinterpret_cast<const uint32_t*>(&sAhi[r0 + 8]);
                ah[mi][3] = *reinterpret_cast<const uint32_t*>(&sAhi[r1 + 8]);
                al[mi][0] = *reinterpret_cast<const uint32_t*>(&sAlo[r0]);
                al[mi][1] = *reinterpret_cast<const uint32_t*>(&sAlo[r1]);
                al[mi][2] = *reinterpret_cast<const uint32_t*>(&sAlo[r0 + 8]);
                al[mi][3] = *reinterpret_cast<const uint32_t*>(&sAlo[r1 + 8]);
            }
            uint32_t bh[8][2], bl[8][2];
#pragma unroll
            for (int ni = 0; ni < 8; ni++) {
                int rb = ((wn << 6) + (ni << 3) + g) * LDA + kk;
                bh[ni][0] = *reinterpret_cast<const uint32_t*>(&sBhi[rb]);
                bh[ni][1] = *reinterpret_cast<const uint32_t*>(&sBhi[rb + 8]);
                bl[ni][0] = *reinterpret_cast<const uint32_t*>(&sBlo[rb]);
                bl[ni][1] = *reinterpret_cast<const uint32_t*>(&sBlo[rb + 8]);
            }
#pragma unroll
            for (int mi = 0; mi < 2; mi++)
#pragma unroll
                for (int ni = 0; ni < 8; ni++) {
                    MMA16816(c[mi][ni][0], c[mi][ni][1], c[mi][ni][2], c[mi][ni][3],
                             ah[mi][0], ah[mi][1], ah[mi][2], ah[mi][3],
                             bh[ni][0], bh[ni][1]);
                    MMA16816(c[mi][ni][0], c[mi][ni][1], c[mi][ni][2], c[mi][ni][3],
                             ah[mi][0], ah[mi][1], ah[mi][2], ah[mi][3],
                             bl[ni][0], bl[ni][1]);
                    MMA16816(c[mi][ni][0], c[mi][ni][1], c[mi][ni][2], c[mi][ni][3],
                             al[mi][0], al[mi][1], al[mi][2], al[mi][3],
                             bh[ni][0], bh[ni][1]);
                }
        }
    }
    __syncthreads();   // operand smem dead; tables overlay it

    // distances in place of accumulators
#pragma unroll
    for (int mi = 0; mi < 2; mi++) {
        int i0 = (wm << 5) + (mi << 4) + g;
#pragma unroll
        for (int ni = 0; ni < 8; ni++) {
            int j0 = (wn << 6) + (ni << 3) + (tg << 1);
            c[mi][ni][0] = sqrtf(fmaxf(sNi[i0]     + sNj[j0]     - 2.f * c[mi][ni][0], 0.f));
            c[mi][ni][1] = sqrtf(fmaxf(sNi[i0]     + sNj[j0 + 1] - 2.f * c[mi][ni][1], 0.f));
            c[mi][ni][2] = sqrtf(fmaxf(sNi[i0 + 8] + sNj[j0]     - 2.f * c[mi][ni][2], 0.f));
            c[mi][ni][3] = sqrtf(fmaxf(sNi[i0 + 8] + sNj[j0 + 1] - 2.f * c[mi][ni][3], 0.f));
        }
    }

    float*  sSR = reinterpret_cast<float*>(smem + OFF_SR);
    float2* sTR = reinterpret_cast<float2*>(smem + OFF_TR);
    float*  sSC = reinterpret_cast<float*>(smem + OFF_SC);
    float2* sTC = reinterpret_cast<float2*>(smem + OFF_TC);

    if (diag) {
        // scatter same-class C values (classes are 16-aligned: class = idx>>4)
        float* sPos = reinterpret_cast<float*>(smem + OFF_SC);
#pragma unroll
        for (int mi = 0; mi < 2; mi++) {
            int ia = (wm << 5) + (mi << 4) + g, ib = ia + 8;
#pragma unroll
            for (int ni = 0; ni < 8; ni++) {
                int j0 = (wn << 6) + (ni << 3) + (tg << 1);
#pragma unroll
                for (int e = 0; e < 2; e++) {
                    int j = j0 + e;
                    if ((ia >> 4) == (j >> 4)) sPos[(ia << 4) + (j & 15)] = MARGIN + c[mi][ni][e];
                    if ((ib >> 4) == (j >> 4)) sPos[(ib << 4) + (j & 15)] = MARGIN + c[mi][ni][2 + e];
                }
            }
        }
        __syncthreads();
        // per-anchor rank sort + suffix sums; build local tables + publish
        if (tid < 128) {
            float v[16];
#pragma unroll
            for (int k = 0; k < 16; k++) v[k] = sPos[(tid << 4) + k];
            float* ss = &sSR[tid * 17];
#pragma unroll
            for (int k = 0; k < 16; k++) {
                float vk = v[k];
                int r = 0;
#pragma unroll
                for (int jj = 0; jj < 16; jj++)
                    r += (int)((v[jj] < vk) | ((v[jj] == vk) & (jj < k)));
                ss[r] = vk;
            }
            size_t ab = (size_t)p * MM + by * 128 + tid;
            float run = 0.f;
            sTR[tid * 17 + 16] = make_float2(0.f, 0.f);
            g_tsuf[ab * 17 + 16] = make_float2(0.f, 0.f);
#pragma unroll
            for (int k = 15; k >= 0; k--) {
                run += ss[k];
                float2 tv = make_float2(run, (float)(16 - k));
                sTR[tid * 17 + k] = tv;
                g_tsuf[ab * 17 + k] = tv;
                g_tsort[ab * 16 + k] = ss[k];
            }
        }
        __threadfence();
        __syncthreads();
        if (tid == 0)
            asm volatile("st.release.gpu.global.b32 [%0], %1;"
                         :: "l"(&g_ready[bid]), "r"(1) : "memory");
    } else {
        // wait for both producer diag CTAs, then load tables
        if (tid == 0) {
            const int* f1 = &g_ready[(p << 2) + by];
            const int* f2 = &g_ready[(p << 2) + bx];
            int r1, r2;
            while (true) {
                asm volatile("ld.acquire.gpu.global.b32 %0, [%1];" : "=r"(r1) : "l"(f1) : "memory");
                asm volatile("ld.acquire.gpu.global.b32 %0, [%1];" : "=r"(r2) : "l"(f2) : "memory");
                if (r1 && r2) break;
                __nanosleep(128);
            }
        }
        __syncthreads();
        size_t rb16 = ((size_t)p * MM + by * 128) * 16;
        size_t rb17 = ((size_t)p * MM + by * 128) * 17;
        size_t cb16 = ((size_t)p * MM + bx * 128) * 16;
        size_t cb17 = ((size_t)p * MM + bx * 128) * 17;
        for (int q = tid; q < 2048; q += 256) {
            sSR[(q >> 4) * 17 + (q & 15)] = g_tsort[rb16 + q];
            sSC[(q >> 4) * 17 + (q & 15)] = g_tsort[cb16 + q];
        }
        for (int q = tid; q < 2176; q += 256) {
            sTR[q] = g_tsuf[rb17 + q];
            sTC[q] = g_tsuf[cb17 + q];
        }
        __syncthreads();
    }

    // hinge searches: row anchors hoisted; col S7/S15 hoisted per column
    const int abase = wm << 5;
    int aIdx[4] = {abase + g, abase + g + 8, abase + 16 + g, abase + 24 + g};
    const float*  SR[4]; const float2* TR[4];
    float S7[4], S15[4];
#pragma unroll
    for (int q = 0; q < 4; q++) {
        SR[q]  = &sSR[aIdx[q] * 17];
        TR[q]  = &sTR[aIdx[q] * 17];
        S7[q]  = SR[q][7];
        S15[q] = SR[q][15];
    }
    float aA = 0.f, aB = 0.f, aC = 0.f;
#pragma unroll
    for (int ni = 0; ni < 8; ni++) {
#pragma unroll
        for (int e = 0; e < 2; e++) {
            int j = (wn << 6) + (ni << 3) + (tg << 1) + e;
            float c7 = 0.f, c15 = 0.f;
            const float* SCj = &sSC[j * 17];
            const float2* TCj = &sTC[j * 17];
            if (!diag) { c7 = SCj[7]; c15 = SCj[15]; }
            int jc = j >> 4;
#pragma unroll
            for (int mi = 0; mi < 2; mi++) {
                float d0 = c[mi][ni][e];
                float d1 = c[mi][ni][2 + e];
                const int q0 = mi << 1, q1 = q0 + 1;
                bool ok0 = !diag || ((aIdx[q0] >> 4) != jc);
                bool ok1 = !diag || ((aIdx[q1] >> 4) != jc);
                if (ok0) search2(SR[q0], TR[q0], S7[q0], S15[q0], d0, aA, aB, aC);
                if (ok1) search2(SR[q1], TR[q1], S7[q1], S15[q1], d1, aA, aB, aC);
                if (!diag) {
                    search2(SCj, TCj, c7, c15, d0, aA, aB, aC);
                    search2(SCj, TCj, c7, c15, d1, aA, aB, aC);
                }
            }
        }
    }

    float loss = aA - aB, cnt = aC;
#pragma unroll
    for (int o = 16; o; o >>= 1) {
        loss += __shfl_xor_sync(0xffffffffu, loss, o);
        cnt  += __shfl_xor_sync(0xffffffffu, cnt, o);
    }
    float* sRed = reinterpret_cast<float*>(smem + OFF_RED);
    if (lane == 0) { sRed[w] = loss; sRed[8 + w] = cnt; }
    __syncthreads();
    if (tid == 0) {
        float L = 0.f, C = 0.f;
#pragma unroll
        for (int k = 0; k < 8; k++) { L += sRed[k]; C += sRed[8 + k]; }
        atomicAdd(&g_psum[p], L);
        atomicAdd(&g_pcnt[p], C);
    }
}

// ---------------------------------------------------------------------------
__global__ void final_kernel(float* __restrict__ out, int out_size) {
    __shared__ float sa[2], sb2[2];
    int t = threadIdx.x;          // 64 threads
    float cnt = g_pcnt[t], sum = g_psum[t];
    float a = (cnt > 0.f) ? sum / fmaxf(cnt, 1.f) : 0.f;
    float b = cnt;
#pragma unroll
    for (int o = 16; o; o >>= 1) {
        a += __shfl_xor_sync(0xffffffffu, a, o);
        b += __shfl_xor_sync(0xffffffffu, b, o);
    }
    if ((t & 31) == 0) { sa[t >> 5] = a; sb2[t >> 5] = b; }
    __syncthreads();
    if (t == 0) {
        out[0] = (sa[0] + sa[1]) / (float)NP;
        if (out_size > 1) out[1] = (sb2[0] + sb2[1]) / (float)NP;
    }
}

extern "C" void kernel_launch(void* const* d_in, const int* in_sizes, int n_in,
                              void* d_out, int out_size) {
    const float* feat = (const float*)d_in[0];
    (void)in_sizes; (void)n_in;

    cudaFuncSetAttribute(fused_kernel, cudaFuncAttributeMaxDynamicSharedMemorySize, SMEM_TOTAL);

    norm_prep_kernel<<<4096, 256>>>(feat);
    fused_kernel<<<640, 256, SMEM_TOTAL>>>(feat);
    final_kernel<<<1, 64>>>((float*)d_out, out_size);
}